// round 16
// baseline (speedup 1.0000x reference)
#include <cuda_runtime.h>
#include <cuda_fp16.h>
#include <cstdint>
#include <cstddef>

// ===================== problem dims =====================
static constexpr int BATCH = 16384;
static constexpr int IN_F  = 2048;
static constexpr int OUT_F = 2048;

// C = A . W   single fp16 x fp16 GEMM, fp32 accum.  y = signed_pow(d, 1/a) epilogue.

// ===================== device scratch =====================
__device__ __half g_A[(size_t)BATCH * IN_F];   // 64 MiB
__device__ __half g_W[(size_t)OUT_F * IN_F];   //  8 MiB

// ===================== helpers =====================
__device__ __forceinline__ uint32_t smem_u32(const void* p) {
    uint32_t a;
    asm("{ .reg .u64 t; cvta.to.shared.u64 t, %1; cvt.u32.u64 %0, t; }" : "=r"(a) : "l"(p));
    return a;
}
__device__ __forceinline__ void cp16(uint32_t smem_dst, const void* gmem_src) {
    asm volatile("cp.async.cg.shared.global [%0], [%1], 16;" :: "r"(smem_dst), "l"(gmem_src));
}
__device__ __forceinline__ void cp_arrive(uint32_t mbar) {
    asm volatile("cp.async.mbarrier.arrive.noinc.shared::cta.b64 [%0];" :: "r"(mbar) : "memory");
}
#define MBAR_INIT(addr, cnt) \
    asm volatile("mbarrier.init.shared.b64 [%0], %1;" :: "r"(addr), "r"(cnt) : "memory")
#define MBAR_ARRIVE(addr) \
    asm volatile("mbarrier.arrive.shared.b64 _, [%0];" :: "r"(addr) : "memory")
#define MBAR_WAIT(addr, ph) do {                                                     \
    uint32_t _m = (addr), _p = (ph), _d;                                             \
    asm volatile("{\n\t.reg .pred p;\n\t"                                            \
        "mbarrier.try_wait.parity.acquire.cta.shared::cta.b64 p, [%1], %2;\n\t"      \
        "selp.b32 %0, 1, 0, p;\n\t}"                                                 \
        : "=r"(_d) : "r"(_m), "r"(_p) : "memory");                                   \
    if (!_d) {                                                                       \
        asm volatile("{\n\t.reg .pred P1;\n\t"                                       \
            "WL%=:\n\t"                                                              \
            "mbarrier.try_wait.parity.acquire.cta.shared::cta.b64 P1, [%0], %1, 0x989680;\n\t" \
            "@P1 bra.uni WD%=;\n\t"                                                  \
            "bra.uni WL%=;\n\t"                                                      \
            "WD%=:\n\t}"                                                             \
            :: "r"(_m), "r"(_p) : "memory");                                         \
    }                                                                                \
} while (0)

__device__ __forceinline__ void ldsm_x4(uint32_t (&r)[4], uint32_t addr) {
    asm volatile("ldmatrix.sync.aligned.m8n8.x4.shared.b16 {%0,%1,%2,%3}, [%4];"
                 : "=r"(r[0]), "=r"(r[1]), "=r"(r[2]), "=r"(r[3]) : "r"(addr));
}
__device__ __forceinline__ void mma_f16(float (&d)[4], const uint32_t (&a)[4],
                                        uint32_t b0, uint32_t b1) {
    asm volatile(
        "mma.sync.aligned.m16n8k16.row.col.f32.f16.f16.f32 "
        "{%0,%1,%2,%3}, {%4,%5,%6,%7}, {%8,%9}, {%0,%1,%2,%3};"
        : "+f"(d[0]), "+f"(d[1]), "+f"(d[2]), "+f"(d[3])
        : "r"(a[0]), "r"(a[1]), "r"(a[2]), "r"(a[3]), "r"(b0), "r"(b1));
}
__device__ __forceinline__ float fast_sqrt(float x) {
    float r;
    asm("sqrt.approx.f32 %0, %1;" : "=f"(r) : "f"(x));
    return r;
}

// SW128 swizzle (Swizzle<3,4,3>) — tile bases must be 1024B aligned
#define SWZ(o) ((o) ^ (((o) >> 3) & 0x70))

// ===================== merged conversion kernel (8 elems/thread, MLP=2) ====================
static constexpr int XB8 = (BATCH * IN_F / 8) / 256;   // 16384 blocks (x part)
static constexpr int WB8 = (OUT_F * IN_F / 8) / 256;   //  2048 blocks (W part)

__global__ void convert_kernel(const float* __restrict__ x,
                               const int* __restrict__ wq,
                               const float* __restrict__ cent,
                               const float* __restrict__ alpha) {
    int bid = blockIdx.x;
    if (bid < XB8) {
        size_t i = (size_t)bid * 256 + threadIdx.x;        // 8-elem index
        float a = alpha[0];
        bool fast = (a == 0.5f);
        const float4* xs = reinterpret_cast<const float4*>(x) + i * 2;
        float4 v0 = xs[0];                                  // two independent loads
        float4 v1 = xs[1];
        float s[8] = {v0.x, v0.y, v0.z, v0.w, v1.x, v1.y, v1.z, v1.w};
        union { __half h[8]; uint4 u; } H;
#pragma unroll
        for (int k = 0; k < 8; k++) {
            float t  = s[k];
            float at = fabsf(t);
            float p  = fast ? fast_sqrt(at) : powf(at, a);
            H.h[k] = __float2half(copysignf(p, t));
        }
        reinterpret_cast<uint4*>(g_A)[i] = H.u;
    } else {
        __shared__ float c[16];
        if (threadIdx.x < 16) c[threadIdx.x] = cent[threadIdx.x];
        __syncthreads();
        size_t i = (size_t)(bid - XB8) * 256 + threadIdx.x; // 8-elem index
        const int4* qs = reinterpret_cast<const int4*>(wq) + i * 2;
        int4 q0 = qs[0];
        int4 q1 = qs[1];
        union { __half h[8]; uint4 u; } H;
        H.h[0] = __float2half(c[q0.x & 15]);
        H.h[1] = __float2half(c[q0.y & 15]);
        H.h[2] = __float2half(c[q0.z & 15]);
        H.h[3] = __float2half(c[q0.w & 15]);
        H.h[4] = __float2half(c[q1.x & 15]);
        H.h[5] = __float2half(c[q1.y & 15]);
        H.h[6] = __float2half(c[q1.z & 15]);
        H.h[7] = __float2half(c[q1.w & 15]);
        reinterpret_cast<uint4*>(g_W)[i] = H.u;
    }
}

// ===================== GEMM kernel (fp16 mma.sync, mbarrier pipeline, 2 CTA/SM) ============
// Frozen at the R14 configuration — measured ceiling for this op (~76% tensor).
static constexpr int BM = 128;
static constexpr int BN = 128;
static constexpr int STAGES = 3;
static constexpr int A_BYTES = BM * 128;          // 16 KiB (128B per row per kc)
static constexpr int B_BYTES = BN * 128;          // 16 KiB
static constexpr int STG = A_BYTES + B_BYTES;     // 32 KiB
static constexpr int MB_OFF = STAGES * STG;       // mbarriers after stages
static constexpr int SMEM_TOTAL = MB_OFF + 64;    // 96 KiB + mbar block
static constexpr int NKC = 32;                    // K=2048 fp16, 64 elems (128B) per kc
static constexpr int NTHR = 256;                  // 8 warps: 4(m) x 2(n), 32x64 warp tile
static constexpr int NB_PER_M = OUT_F / BN;       // 16 n-blocks
static constexpr int ROW_B = IN_F * 2;            // 4096 B (both A and W)

__global__ void __launch_bounds__(NTHR, 2)
gemm_kernel(float* __restrict__ out, const float* __restrict__ alpha) {
    extern __shared__ char smem_raw[];
    uint32_t sb = smem_u32(smem_raw);
    const uint32_t mb_full  = sb + MB_OFF;
    const uint32_t mb_empty = sb + MB_OFF + 24;

    const int tid = threadIdx.x;
    const int wid = tid >> 5, lane = tid & 31;
    const int warp_m = wid & 3, warp_n = wid >> 2;          // 4 x 2 warps
    const int mb = blockIdx.x >> 4, nb = blockIdx.x & 15;   // n-minor: L2 A reuse
    const int m0 = mb * BM, n0 = nb * BN;

    if (tid == 0) {
#pragma unroll
        for (int s = 0; s < STAGES; s++) {
            MBAR_INIT(mb_full + 8 * s, NTHR);
            MBAR_INIT(mb_empty + 8 * s, NTHR);
        }
    }
    __syncthreads();

    const int ld_row = tid >> 3, ld_col = tid & 7;
    const char* baseA = (const char*)g_A + (size_t)(m0 + ld_row) * ROW_B + ld_col * 16;
    const char* baseW = (const char*)g_W + (size_t)(n0 + ld_row) * ROW_B + ld_col * 16;
    const uint32_t dst0 = SWZ(ld_row * 128 + ld_col * 16);

    const int a_row  = warp_m * 32 + (lane & 15);
    const int a_ext  = (lane >> 4) * 16;
    const int b_row  = warp_n * 64 + (lane & 7) + ((lane >> 4) << 3);
    const int b_ext  = ((lane >> 3) & 1) * 16;

    float acc[2][8][4];
#pragma unroll
    for (int im = 0; im < 2; im++)
#pragma unroll
        for (int in = 0; in < 8; in++)
#pragma unroll
            for (int r = 0; r < 4; r++) acc[im][in][r] = 0.0f;

    auto fill_stage = [&](int slot, int kc) {
        int off = kc * 128;
        uint32_t sA = sb + slot * STG;
        uint32_t sB = sA + A_BYTES;
#pragma unroll
        for (int i = 0; i < 4; i++)
            cp16(sA + dst0 + i * (32 * 128), baseA + (size_t)i * 32 * ROW_B + off);
#pragma unroll
        for (int i = 0; i < 4; i++)
            cp16(sB + dst0 + i * (32 * 128), baseW + (size_t)i * 32 * ROW_B + off);
        cp_arrive(mb_full + 8 * slot);
    };

    auto load_frags = [&](uint32_t (&af)[2][4], uint32_t (&bfr)[4][4],
                          uint32_t sA, uint32_t sB, int ks) {
#pragma unroll
        for (int im = 0; im < 2; im++)
            ldsm_x4(af[im], sA + SWZ((a_row + im * 16) * 128 + ks * 32 + a_ext));
#pragma unroll
        for (int jn = 0; jn < 4; jn++)
            ldsm_x4(bfr[jn], sB + SWZ((b_row + jn * 16) * 128 + ks * 32 + b_ext));
    };
    auto do_mmas = [&](const uint32_t (&af)[2][4], const uint32_t (&bfr)[4][4]) {
#pragma unroll
        for (int im = 0; im < 2; im++)
#pragma unroll
            for (int jn = 0; jn < 4; jn++) {
                mma_f16(acc[im][2 * jn + 0], af[im], bfr[jn][0], bfr[jn][1]);
                mma_f16(acc[im][2 * jn + 1], af[im], bfr[jn][2], bfr[jn][3]);
            }
    };

    int cs = 0, cph = 0;
    int ps = 0, pph = 1;

#pragma unroll
    for (int s = 0; s < STAGES - 1; s++) {
        MBAR_WAIT(mb_empty + 8 * ps, pph);
        fill_stage(ps, s);
        if (++ps == STAGES) { ps = 0; pph ^= 1; }
    }

    uint32_t af[2][2][4], bfr[2][4][4];
    for (int kc = 0; kc < NKC; kc++) {
        MBAR_WAIT(mb_full + 8 * cs, cph);

        uint32_t sA = sb + cs * STG;
        uint32_t sB = sA + A_BYTES;

        load_frags(af[0], bfr[0], sA, sB, 0);

        int nkc = kc + STAGES - 1;
        if (nkc < NKC) {
            MBAR_WAIT(mb_empty + 8 * ps, pph);
            fill_stage(ps, nkc);
            if (++ps == STAGES) { ps = 0; pph ^= 1; }
        }

        load_frags(af[1], bfr[1], sA, sB, 1);
        do_mmas(af[0], bfr[0]);
        load_frags(af[0], bfr[0], sA, sB, 2);
        do_mmas(af[1], bfr[1]);
        load_frags(af[1], bfr[1], sA, sB, 3);
        MBAR_ARRIVE(mb_empty + 8 * cs);
        do_mmas(af[0], bfr[0]);
        do_mmas(af[1], bfr[1]);

        if (++cs == STAGES) { cs = 0; cph ^= 1; }
    }

    // ---- epilogue: y = sign(d) * |d|^(1/a) ----
    float a = alpha[0];
    bool fast = (a == 0.5f);
    float inv = 1.0f / a;
    const int er = m0 + warp_m * 32 + (lane >> 2);
    const int ec = n0 + warp_n * 64 + (lane & 3) * 2;
#pragma unroll
    for (int im = 0; im < 2; im++) {
#pragma unroll
        for (int in = 0; in < 8; in++) {
            float d0 = acc[im][in][0], d1 = acc[im][in][1];
            float d2 = acc[im][in][2], d3 = acc[im][in][3];
            float2 v01, v23;
            if (fast) {
                v01.x = d0 * fabsf(d0); v01.y = d1 * fabsf(d1);
                v23.x = d2 * fabsf(d2); v23.y = d3 * fabsf(d3);
            } else {
                v01.x = copysignf(powf(fabsf(d0), inv), d0);
                v01.y = copysignf(powf(fabsf(d1), inv), d1);
                v23.x = copysignf(powf(fabsf(d2), inv), d2);
                v23.y = copysignf(powf(fabsf(d3), inv), d3);
            }
            int jn = in >> 1, b = in & 1;
            int row = er + im * 16;
            int col = ec + jn * 16 + b * 8;
            *reinterpret_cast<float2*>(out + (size_t)row * OUT_F + col) = v01;
            *reinterpret_cast<float2*>(out + (size_t)(row + 8) * OUT_F + col) = v23;
        }
    }
}

// ===================== launch =====================
extern "C" void kernel_launch(void* const* d_in, const int* in_sizes, int n_in,
                              void* d_out, int out_size) {
    const float* x = nullptr;
    const float* cent = nullptr;
    const float* alpha = nullptr;
    const int*   wq = nullptr;
    for (int i = 0; i < n_in; i++) {
        long s = in_sizes[i];
        if      (s == (long)BATCH * IN_F) x     = (const float*)d_in[i];
        else if (s == 16)                 cent  = (const float*)d_in[i];
        else if (s == 1)                  alpha = (const float*)d_in[i];
        else if (s == (long)OUT_F * IN_F) wq    = (const int*)d_in[i];
    }

    cudaFuncSetAttribute(gemm_kernel, cudaFuncAttributeMaxDynamicSharedMemorySize, SMEM_TOTAL);

    convert_kernel<<<XB8 + WB8, 256>>>(x, wq, cent, alpha);
    gemm_kernel<<<(BATCH / BM) * NB_PER_M, NTHR, SMEM_TOTAL>>>((float*)d_out, alpha);
}

// round 17
// speedup vs baseline: 1.4945x; 1.4945x over previous
#include <cuda_runtime.h>
#include <cuda_fp16.h>
#include <cstdint>
#include <cstddef>

// ===================== problem dims =====================
static constexpr int BATCH = 16384;
static constexpr int IN_F  = 2048;
static constexpr int OUT_F = 2048;

// C = A . W   single fp16 x fp16 GEMM, fp32 accum.  y = signed_pow(d, 1/a) epilogue.

// ===================== device scratch =====================
__device__ __half g_A[(size_t)BATCH * IN_F];   // 64 MiB
__device__ __half g_W[(size_t)OUT_F * IN_F];   //  8 MiB

// ===================== helpers =====================
__device__ __forceinline__ uint32_t smem_u32(const void* p) {
    uint32_t a;
    asm("{ .reg .u64 t; cvta.to.shared.u64 t, %1; cvt.u32.u64 %0, t; }" : "=r"(a) : "l"(p));
    return a;
}
__device__ __forceinline__ void cp16(uint32_t smem_dst, const void* gmem_src) {
    asm volatile("cp.async.cg.shared.global [%0], [%1], 16;" :: "r"(smem_dst), "l"(gmem_src));
}
__device__ __forceinline__ void cp_arrive(uint32_t mbar) {
    asm volatile("cp.async.mbarrier.arrive.noinc.shared::cta.b64 [%0];" :: "r"(mbar) : "memory");
}
#define MBAR_INIT(addr, cnt) \
    asm volatile("mbarrier.init.shared.b64 [%0], %1;" :: "r"(addr), "r"(cnt) : "memory")
#define MBAR_ARRIVE(addr) \
    asm volatile("mbarrier.arrive.shared.b64 _, [%0];" :: "r"(addr) : "memory")
#define MBAR_WAIT(addr, ph) do {                                                     \
    uint32_t _m = (addr), _p = (ph), _d;                                             \
    asm volatile("{\n\t.reg .pred p;\n\t"                                            \
        "mbarrier.try_wait.parity.acquire.cta.shared::cta.b64 p, [%1], %2;\n\t"      \
        "selp.b32 %0, 1, 0, p;\n\t}"                                                 \
        : "=r"(_d) : "r"(_m), "r"(_p) : "memory");                                   \
    if (!_d) {                                                                       \
        asm volatile("{\n\t.reg .pred P1;\n\t"                                       \
            "WL%=:\n\t"                                                              \
            "mbarrier.try_wait.parity.acquire.cta.shared::cta.b64 P1, [%0], %1, 0x989680;\n\t" \
            "@P1 bra.uni WD%=;\n\t"                                                  \
            "bra.uni WL%=;\n\t"                                                      \
            "WD%=:\n\t}"                                                             \
            :: "r"(_m), "r"(_p) : "memory");                                         \
    }                                                                                \
} while (0)

__device__ __forceinline__ void ldsm_x4(uint32_t (&r)[4], uint32_t addr) {
    asm volatile("ldmatrix.sync.aligned.m8n8.x4.shared.b16 {%0,%1,%2,%3}, [%4];"
                 : "=r"(r[0]), "=r"(r[1]), "=r"(r[2]), "=r"(r[3]) : "r"(addr));
}
__device__ __forceinline__ void mma_f16(float (&d)[4], const uint32_t (&a)[4],
                                        uint32_t b0, uint32_t b1) {
    asm volatile(
        "mma.sync.aligned.m16n8k16.row.col.f32.f16.f16.f32 "
        "{%0,%1,%2,%3}, {%4,%5,%6,%7}, {%8,%9}, {%0,%1,%2,%3};"
        : "+f"(d[0]), "+f"(d[1]), "+f"(d[2]), "+f"(d[3])
        : "r"(a[0]), "r"(a[1]), "r"(a[2]), "r"(a[3]), "r"(b0), "r"(b1));
}
__device__ __forceinline__ float fast_sqrt(float x) {
    float r;
    asm("sqrt.approx.f32 %0, %1;" : "=f"(r) : "f"(x));
    return r;
}

// SW128 swizzle (Swizzle<3,4,3>) — tile bases must be 1024B aligned
#define SWZ(o) ((o) ^ (((o) >> 3) & 0x70))

// ===================== merged conversion kernel (8 elems/thread, MLP=2) ====================
static constexpr int XB8 = (BATCH * IN_F / 8) / 256;   // 16384 blocks (x part)
static constexpr int WB8 = (OUT_F * IN_F / 8) / 256;   //  2048 blocks (W part)

__global__ void convert_kernel(const float* __restrict__ x,
                               const int* __restrict__ wq,
                               const float* __restrict__ cent,
                               const float* __restrict__ alpha) {
    int bid = blockIdx.x;
    if (bid < XB8) {
        size_t i = (size_t)bid * 256 + threadIdx.x;        // 8-elem index
        float a = alpha[0];
        bool fast = (a == 0.5f);
        const float4* xs = reinterpret_cast<const float4*>(x) + i * 2;
        float4 v0 = xs[0];                                  // two independent loads
        float4 v1 = xs[1];
        float s[8] = {v0.x, v0.y, v0.z, v0.w, v1.x, v1.y, v1.z, v1.w};
        union { __half h[8]; uint4 u; } H;
#pragma unroll
        for (int k = 0; k < 8; k++) {
            float t  = s[k];
            float at = fabsf(t);
            float p  = fast ? fast_sqrt(at) : powf(at, a);
            H.h[k] = __float2half(copysignf(p, t));
        }
        reinterpret_cast<uint4*>(g_A)[i] = H.u;
    } else {
        __shared__ float c[16];
        if (threadIdx.x < 16) c[threadIdx.x] = cent[threadIdx.x];
        __syncthreads();
        size_t i = (size_t)(bid - XB8) * 256 + threadIdx.x; // 8-elem index
        const int4* qs = reinterpret_cast<const int4*>(wq) + i * 2;
        int4 q0 = qs[0];
        int4 q1 = qs[1];
        union { __half h[8]; uint4 u; } H;
        H.h[0] = __float2half(c[q0.x & 15]);
        H.h[1] = __float2half(c[q0.y & 15]);
        H.h[2] = __float2half(c[q0.z & 15]);
        H.h[3] = __float2half(c[q0.w & 15]);
        H.h[4] = __float2half(c[q1.x & 15]);
        H.h[5] = __float2half(c[q1.y & 15]);
        H.h[6] = __float2half(c[q1.z & 15]);
        H.h[7] = __float2half(c[q1.w & 15]);
        reinterpret_cast<uint4*>(g_W)[i] = H.u;
    }
}

// ===================== GEMM kernel (fp16 mma.sync, mbarrier pipeline, 2 CTA/SM) ============
// Frozen at the R14 configuration — measured ceiling for this op (~76% tensor).
static constexpr int BM = 128;
static constexpr int BN = 128;
static constexpr int STAGES = 3;
static constexpr int A_BYTES = BM * 128;          // 16 KiB (128B per row per kc)
static constexpr int B_BYTES = BN * 128;          // 16 KiB
static constexpr int STG = A_BYTES + B_BYTES;     // 32 KiB
static constexpr int MB_OFF = STAGES * STG;       // mbarriers after stages
static constexpr int SMEM_TOTAL = MB_OFF + 64;    // 96 KiB + mbar block
static constexpr int NKC = 32;                    // K=2048 fp16, 64 elems (128B) per kc
static constexpr int NTHR = 256;                  // 8 warps: 4(m) x 2(n), 32x64 warp tile
static constexpr int NB_PER_M = OUT_F / BN;       // 16 n-blocks
static constexpr int ROW_B = IN_F * 2;            // 4096 B (both A and W)

__global__ void __launch_bounds__(NTHR, 2)
gemm_kernel(float* __restrict__ out, const float* __restrict__ alpha) {
    extern __shared__ char smem_raw[];
    uint32_t sb = smem_u32(smem_raw);
    const uint32_t mb_full  = sb + MB_OFF;
    const uint32_t mb_empty = sb + MB_OFF + 24;

    const int tid = threadIdx.x;
    const int wid = tid >> 5, lane = tid & 31;
    const int warp_m = wid & 3, warp_n = wid >> 2;          // 4 x 2 warps
    const int mb = blockIdx.x >> 4, nb = blockIdx.x & 15;   // n-minor: L2 A reuse
    const int m0 = mb * BM, n0 = nb * BN;

    if (tid == 0) {
#pragma unroll
        for (int s = 0; s < STAGES; s++) {
            MBAR_INIT(mb_full + 8 * s, NTHR);
            MBAR_INIT(mb_empty + 8 * s, NTHR);
        }
    }
    __syncthreads();

    const int ld_row = tid >> 3, ld_col = tid & 7;
    const char* baseA = (const char*)g_A + (size_t)(m0 + ld_row) * ROW_B + ld_col * 16;
    const char* baseW = (const char*)g_W + (size_t)(n0 + ld_row) * ROW_B + ld_col * 16;
    const uint32_t dst0 = SWZ(ld_row * 128 + ld_col * 16);

    const int a_row  = warp_m * 32 + (lane & 15);
    const int a_ext  = (lane >> 4) * 16;
    const int b_row  = warp_n * 64 + (lane & 7) + ((lane >> 4) << 3);
    const int b_ext  = ((lane >> 3) & 1) * 16;

    float acc[2][8][4];
#pragma unroll
    for (int im = 0; im < 2; im++)
#pragma unroll
        for (int in = 0; in < 8; in++)
#pragma unroll
            for (int r = 0; r < 4; r++) acc[im][in][r] = 0.0f;

    auto fill_stage = [&](int slot, int kc) {
        int off = kc * 128;
        uint32_t sA = sb + slot * STG;
        uint32_t sB = sA + A_BYTES;
#pragma unroll
        for (int i = 0; i < 4; i++)
            cp16(sA + dst0 + i * (32 * 128), baseA + (size_t)i * 32 * ROW_B + off);
#pragma unroll
        for (int i = 0; i < 4; i++)
            cp16(sB + dst0 + i * (32 * 128), baseW + (size_t)i * 32 * ROW_B + off);
        cp_arrive(mb_full + 8 * slot);
    };

    auto load_frags = [&](uint32_t (&af)[2][4], uint32_t (&bfr)[4][4],
                          uint32_t sA, uint32_t sB, int ks) {
#pragma unroll
        for (int im = 0; im < 2; im++)
            ldsm_x4(af[im], sA + SWZ((a_row + im * 16) * 128 + ks * 32 + a_ext));
#pragma unroll
        for (int jn = 0; jn < 4; jn++)
            ldsm_x4(bfr[jn], sB + SWZ((b_row + jn * 16) * 128 + ks * 32 + b_ext));
    };
    auto do_mmas = [&](const uint32_t (&af)[2][4], const uint32_t (&bfr)[4][4]) {
#pragma unroll
        for (int im = 0; im < 2; im++)
#pragma unroll
            for (int jn = 0; jn < 4; jn++) {
                mma_f16(acc[im][2 * jn + 0], af[im], bfr[jn][0], bfr[jn][1]);
                mma_f16(acc[im][2 * jn + 1], af[im], bfr[jn][2], bfr[jn][3]);
            }
    };

    int cs = 0, cph = 0;
    int ps = 0, pph = 1;

#pragma unroll
    for (int s = 0; s < STAGES - 1; s++) {
        MBAR_WAIT(mb_empty + 8 * ps, pph);
        fill_stage(ps, s);
        if (++ps == STAGES) { ps = 0; pph ^= 1; }
    }

    uint32_t af[2][2][4], bfr[2][4][4];
    for (int kc = 0; kc < NKC; kc++) {
        MBAR_WAIT(mb_full + 8 * cs, cph);

        uint32_t sA = sb + cs * STG;
        uint32_t sB = sA + A_BYTES;

        load_frags(af[0], bfr[0], sA, sB, 0);

        int nkc = kc + STAGES - 1;
        if (nkc < NKC) {
            MBAR_WAIT(mb_empty + 8 * ps, pph);
            fill_stage(ps, nkc);
            if (++ps == STAGES) { ps = 0; pph ^= 1; }
        }

        load_frags(af[1], bfr[1], sA, sB, 1);
        do_mmas(af[0], bfr[0]);
        load_frags(af[0], bfr[0], sA, sB, 2);
        do_mmas(af[1], bfr[1]);
        load_frags(af[1], bfr[1], sA, sB, 3);
        MBAR_ARRIVE(mb_empty + 8 * cs);
        do_mmas(af[0], bfr[0]);
        do_mmas(af[1], bfr[1]);

        if (++cs == STAGES) { cs = 0; cph ^= 1; }
    }

    // ---- epilogue: y = sign(d) * |d|^(1/a) ----
    float a = alpha[0];
    bool fast = (a == 0.5f);
    float inv = 1.0f / a;
    const int er = m0 + warp_m * 32 + (lane >> 2);
    const int ec = n0 + warp_n * 64 + (lane & 3) * 2;
#pragma unroll
    for (int im = 0; im < 2; im++) {
#pragma unroll
        for (int in = 0; in < 8; in++) {
            float d0 = acc[im][in][0], d1 = acc[im][in][1];
            float d2 = acc[im][in][2], d3 = acc[im][in][3];
            float2 v01, v23;
            if (fast) {
                v01.x = d0 * fabsf(d0); v01.y = d1 * fabsf(d1);
                v23.x = d2 * fabsf(d2); v23.y = d3 * fabsf(d3);
            } else {
                v01.x = copysignf(powf(fabsf(d0), inv), d0);
                v01.y = copysignf(powf(fabsf(d1), inv), d1);
                v23.x = copysignf(powf(fabsf(d2), inv), d2);
                v23.y = copysignf(powf(fabsf(d3), inv), d3);
            }
            int jn = in >> 1, b = in & 1;
            int row = er + im * 16;
            int col = ec + jn * 16 + b * 8;
            *reinterpret_cast<float2*>(out + (size_t)row * OUT_F + col) = v01;
            *reinterpret_cast<float2*>(out + (size_t)(row + 8) * OUT_F + col) = v23;
        }
    }
}

// ===================== launch =====================
extern "C" void kernel_launch(void* const* d_in, const int* in_sizes, int n_in,
                              void* d_out, int out_size) {
    const float* x = nullptr;
    const float* cent = nullptr;
    const float* alpha = nullptr;
    const int*   wq = nullptr;
    for (int i = 0; i < n_in; i++) {
        long s = in_sizes[i];
        if      (s == (long)BATCH * IN_F) x     = (const float*)d_in[i];
        else if (s == 16)                 cent  = (const float*)d_in[i];
        else if (s == 1)                  alpha = (const float*)d_in[i];
        else if (s == (long)OUT_F * IN_F) wq    = (const int*)d_in[i];
    }

    cudaFuncSetAttribute(gemm_kernel, cudaFuncAttributeMaxDynamicSharedMemorySize, SMEM_TOTAL);

    convert_kernel<<<XB8 + WB8, 256>>>(x, wq, cent, alpha);
    gemm_kernel<<<(BATCH / BM) * NB_PER_M, NTHR, SMEM_TOTAL>>>((float*)d_out, alpha);
}